// round 6
// baseline (speedup 1.0000x reference)
#include <cuda_runtime.h>
#include <cstdint>

#define B_  64
#define S_  512
#define H_  1024
#define L_  64
#define M_  (B_ * S_)      // 32768 rows

typedef unsigned long long u64;

// ---------------- scratch (no allocations allowed) ----------------
__device__ float g_llh[B_];
__device__ int   g_done;     // zero-init; reset by last CTA each launch

// ---------------- f32x2 helpers (sm_100+, PTX ISA 8.6) ----------------
__device__ __forceinline__ u64 pack2(float lo, float hi) {
    u64 r;
    asm("mov.b64 %0, {%1, %2};" : "=l"(r) : "f"(lo), "f"(hi));
    return r;
}
__device__ __forceinline__ void fma2(u64 &d, u64 a, u64 b) {
    asm("fma.rn.f32x2 %0, %1, %2, %0;" : "+l"(d) : "l"(a), "l"(b));
}
__device__ __forceinline__ u64 add2(u64 a, u64 b) {
    u64 r;
    asm("add.rn.f32x2 %0, %1, %2;" : "=l"(r) : "l"(a), "l"(b));
    return r;
}
__device__ __forceinline__ float2 unpk2(u64 v) {
    float2 r;
    asm("mov.b64 {%0, %1}, %2;" : "=f"(r.x), "=f"(r.y) : "l"(v));
    return r;
}

// ================= Emissions GEMM (f32x2) — unchanged from R5 (~43us) =================
#define BM 128
#define BN 64
#define BK 16
#define AS_ROW (BM / 4 + 1)

__global__ __launch_bounds__(256) void gemm_kernel(
    const float* __restrict__ hs,
    const float* __restrict__ W,
    const float* __restrict__ bias,
    float* __restrict__ out)
{
    __shared__ float4 As4[BK][AS_ROW];
    __shared__ u64    Bs2[BK][32];

    const int tid = threadIdx.x;
    const int m0  = blockIdx.x * BM;
    const int tx  = tid & 15;
    const int ty  = tid >> 4;

    const int a_row = tid >> 2;
    const int a_k   = (tid & 3) * 4;
    const float* hsA0 = hs + (size_t)(m0 + a_row)      * H_ + a_k;
    const float* hsA1 = hs + (size_t)(m0 + a_row + 64) * H_ + a_k;
    const int b_k  = tid >> 4;
    const int b_c4 = tid & 15;
    const float* Wp = W + (size_t)b_k * L_ + b_c4 * 4;

    u64 acc[8][2];
    #pragma unroll
    for (int p = 0; p < 8; ++p) { acc[p][0] = 0ull; acc[p][1] = 0ull; }

    float4 a0 = *(const float4*)hsA0;
    float4 a1 = *(const float4*)hsA1;
    float4 bw = *(const float4*)Wp;

    float* As_f = (float*)As4;

    const int NCH = H_ / BK;
    for (int kc = 0; kc < NCH; ++kc) {
        As_f[(a_k + 0) * (AS_ROW * 4) + a_row] = a0.x;
        As_f[(a_k + 1) * (AS_ROW * 4) + a_row] = a0.y;
        As_f[(a_k + 2) * (AS_ROW * 4) + a_row] = a0.z;
        As_f[(a_k + 3) * (AS_ROW * 4) + a_row] = a0.w;
        As_f[(a_k + 0) * (AS_ROW * 4) + a_row + 64] = a1.x;
        As_f[(a_k + 1) * (AS_ROW * 4) + a_row + 64] = a1.y;
        As_f[(a_k + 2) * (AS_ROW * 4) + a_row + 64] = a1.z;
        As_f[(a_k + 3) * (AS_ROW * 4) + a_row + 64] = a1.w;
        Bs2[b_k][b_c4]      = pack2(bw.x, bw.y);
        Bs2[b_k][16 + b_c4] = pack2(bw.z, bw.w);
        __syncthreads();

        if (kc + 1 < NCH) {
            a0 = *(const float4*)(hsA0 + (kc + 1) * BK);
            a1 = *(const float4*)(hsA1 + (kc + 1) * BK);
            bw = *(const float4*)(Wp + (size_t)(kc + 1) * BK * L_);
        }

        #pragma unroll
        for (int kk = 0; kk < BK; ++kk) {
            const float4 av0 = As4[kk][ty * 2];
            const float4 av1 = As4[kk][ty * 2 + 1];
            const u64 b0 = Bs2[kk][tx];
            const u64 b1 = Bs2[kk][16 + tx];
            u64 ad[8];
            ad[0] = pack2(av0.x, av0.x); ad[1] = pack2(av0.y, av0.y);
            ad[2] = pack2(av0.z, av0.z); ad[3] = pack2(av0.w, av0.w);
            ad[4] = pack2(av1.x, av1.x); ad[5] = pack2(av1.y, av1.y);
            ad[6] = pack2(av1.z, av1.z); ad[7] = pack2(av1.w, av1.w);
            #pragma unroll
            for (int p = 0; p < 8; ++p) {
                fma2(acc[p][0], ad[p], b0);
                fma2(acc[p][1], ad[p], b1);
            }
        }
        __syncthreads();
    }

    float bb[4];
    #pragma unroll
    for (int q = 0; q < 4; ++q) bb[q] = bias[tx * 4 + q];

    #pragma unroll
    for (int p = 0; p < 8; ++p) {
        const size_t r = (size_t)(m0 + ty * 8 + p) * L_ + tx * 4;
        const float2 v0 = unpk2(acc[p][0]);
        const float2 v1 = unpk2(acc[p][1]);
        out[r + 0] = v0.x + bb[0];
        out[r + 1] = v0.y + bb[1];
        out[r + 2] = v1.x + bb[2];
        out[r + 3] = v1.y + bb[3];
    }
}

// ================= CRF kernel: single warp per batch =================
// Lane j owns labels c0=2j, c1=2j+1. q kept as 32 packed u64 pairs in smem.
// Per step: 16 LDS.128 (broadcast), 64 fma2, exps precomputed at prefetch,
// 1 STS.64, 1 __syncwarp. No block barrier.
__global__ __launch_bounds__(32, 1) void crf_kernel(
    const float* __restrict__ em,          // [B,S,L] (4B-aligned only!)
    const int*   __restrict__ mask,        // [B,S]
    const int*   __restrict__ labels,      // [B,S] int32
    const float* __restrict__ start_t,     // [L]
    const float* __restrict__ end_t,       // [L]
    const float* __restrict__ trans,       // [L,L]
    float* __restrict__ loss_out)
{
    const int b = blockIdx.x;
    const int j = threadIdx.x;          // 0..31
    const int c0 = 2 * j, c1 = 2 * j + 1;
    const unsigned FULL = 0xffffffffu;

    __shared__ ulonglong2 qsm[2][16];   // [buf][i]: 4 q values per entry

    // ---- sequence length (mask is a prefix) ----
    int cnt = 0;
    {
        const int* mrow = mask + (size_t)b * S_;
        #pragma unroll 4
        for (int t = j; t < S_; t += 32) cnt += mrow[t];
    }
    #pragma unroll
    for (int s = 16; s > 0; s >>= 1) cnt += __shfl_xor_sync(FULL, cnt, s);
    const int len = cnt;

    // ---- per-lane constants: E packed over i-pairs, one array per owned col ----
    // EpX[k] = ( exp(trans[2k][cX]), exp(trans[2k+1][cX]) ), matching q-pair layout.
    u64 EpA[32], EpB[32];
    #pragma unroll
    for (int k = 0; k < 32; ++k) {
        EpA[k] = pack2(__expf(trans[(2 * k) * L_ + c0]), __expf(trans[(2 * k + 1) * L_ + c0]));
        EpB[k] = pack2(__expf(trans[(2 * k) * L_ + c1]), __expf(trans[(2 * k + 1) * L_ + c1]));
    }
    const float eEnd0 = __expf(end_t[c0]);
    const float eEnd1 = __expf(end_t[c1]);

    const float* emb = em + (size_t)b * S_ * L_;

    // ---- init: alpha0 = start + em[0], renorm by warp max ----
    const float al0 = start_t[c0] + emb[c0];
    const float al1 = start_t[c1] + emb[c1];
    float mx = fmaxf(al0, al1);
    #pragma unroll
    for (int s = 16; s > 0; s >>= 1) mx = fmaxf(mx, __shfl_xor_sync(FULL, mx, s));
    float c = mx;
    float q0s = __expf(al0 - mx);
    float q1s = __expf(al1 - mx);
    ((u64*)qsm[0])[j] = pack2(q0s, q1s);
    __syncwarp();

    // ---- exp(em) prefetch, depth 2 (exps computed at load time) ----
    float2 exA, exB;
    if (len > 1) { exA.x = __expf(emb[(size_t)1 * L_ + c0]); exA.y = __expf(emb[(size_t)1 * L_ + c1]); }
    else         { exA.x = exA.y = 1.0f; }
    if (len > 2) { exB.x = __expf(emb[(size_t)2 * L_ + c0]); exB.y = __expf(emb[(size_t)2 * L_ + c1]); }
    else         { exB.x = exB.y = 1.0f; }

    // ---- main scan ----
    float pending = 1.0f;
    int prev = 0;
    for (int t = 1; t < len; ++t) {
        const float2 ex = exA;
        exA = exB;
        if (t + 2 < len) {
            exB.x = __expf(emb[(size_t)(t + 2) * L_ + c0]);
            exB.y = __expf(emb[(size_t)(t + 2) * L_ + c1]);
        }

        u64 aA[4] = {0ull, 0ull, 0ull, 0ull};
        u64 aB[4] = {0ull, 0ull, 0ull, 0ull};
        const ulonglong2* qp = qsm[prev];
        #pragma unroll
        for (int i = 0; i < 16; ++i) {
            const ulonglong2 u = qp[i];
            fma2(aA[i & 3], u.x, EpA[2 * i]);
            fma2(aA[i & 3], u.y, EpA[2 * i + 1]);
            fma2(aB[i & 3], u.x, EpB[2 * i]);
            fma2(aB[i & 3], u.y, EpB[2 * i + 1]);
        }
        const float2 vA = unpk2(add2(add2(aA[0], aA[1]), add2(aA[2], aA[3])));
        const float2 vB = unpk2(add2(add2(aB[0], aB[1]), add2(aB[2], aB[3])));
        q0s = (vA.x + vA.y) * ex.x * pending;
        q1s = (vB.x + vB.y) * ex.y * pending;

        const int cur = prev ^ 1;
        ((u64*)qsm[cur])[j] = pack2(q0s, q1s);
        __syncwarp();

        if ((t & 7) == 0) {
            float m = fmaxf(q0s, q1s);
            #pragma unroll
            for (int s = 16; s > 0; s >>= 1) m = fmaxf(m, __shfl_xor_sync(FULL, m, s));
            pending = 1.0f / m;
            c += __logf(m);
        } else {
            pending = 1.0f;
        }
        prev = cur;
    }

    // ---- log_z = c + log(pending) + log(sum q*exp(end)) ----
    float sv = q0s * eEnd0 + q1s * eEnd1;
    #pragma unroll
    for (int s = 16; s > 0; s >>= 1) sv += __shfl_xor_sync(FULL, sv, s);
    const float logz = c + __logf(pending) + __logf(sv);

    // ---- numerator (strided over t); indices clamped ----
    const int* lab = labels + (size_t)b * S_;
    float part = 0.0f;
    for (int t = 1 + j; t < len; t += 32) {
        const int lp = lab[t - 1];
        const int lc = lab[t];
        const int tp = ((lp == -100) ? 0 : lp) & 63;
        const int tc = ((lc == -100) ? 0 : lc) & 63;
        part += trans[tp * L_ + tc] + emb[(size_t)t * L_ + tc];
    }
    if (j == 0) {
        const int l0 = lab[0];
        const int t0 = ((l0 == -100) ? 0 : l0) & 63;
        const int ll = lab[len - 1];
        const int tl = ((ll == -100) ? 0 : ll) & 63;
        part += start_t[t0] + emb[t0] + end_t[tl];
    }
    #pragma unroll
    for (int s = 16; s > 0; s >>= 1) part += __shfl_xor_sync(FULL, part, s);

    // ---- fused loss: last CTA reduces all llh ----
    if (j == 0) {
        g_llh[b] = part - logz;
        __threadfence();
        const int old = atomicAdd(&g_done, 1);
        if (old == B_ - 1) {
            float sum = 0.0f;
            #pragma unroll 8
            for (int i = 0; i < B_; ++i) sum += __ldcg(&g_llh[i]);
            loss_out[0] = -sum / (float)B_;
            g_done = 0;   // reset for next graph replay
        }
    }
}

// ================= launch =================
extern "C" void kernel_launch(void* const* d_in, const int* in_sizes, int n_in,
                              void* d_out, int out_size)
{
    const float* hs     = (const float*)d_in[0];
    const int*   mask   = (const int*)d_in[1];
    const int*   labels = (const int*)d_in[2];
    const float* W      = (const float*)d_in[3];
    const float* bias   = (const float*)d_in[4];
    const float* st     = (const float*)d_in[5];
    const float* en     = (const float*)d_in[6];
    const float* tr     = (const float*)d_in[7];

    float* out = (float*)d_out;
    const int off = (out_size > M_ * L_) ? (out_size - M_ * L_) : 0;
    float* emis = out + off;

    gemm_kernel<<<M_ / BM, 256>>>(hs, W, bias, emis);
    crf_kernel<<<B_, 32>>>(emis, mask, labels, st, en, tr, out);
}